// round 1
// baseline (speedup 1.0000x reference)
#include <cuda_runtime.h>
#include <math.h>

#define BATCH 2
#define SEQ   2048
#define CH    512
#define HEADS 8
#define DH    64
#define WIN   64
#define RANK  8
#define NGLOB (SEQ / WIN)          // 32
#define LSCALE 0.25f               // 2.0 / R
#define QKVC  (3 * CH)             // 1536
#define ROWS  (BATCH * SEQ)        // 4096

// ---------------- device scratch (no allocations allowed) ----------------
__device__ float g_wqkv_eff[CH * QKVC];     // 512 x 1536
__device__ float g_wout_eff[CH * CH];       // 512 x 512
__device__ float g_qkv[ROWS * QKVC];        // 4096 x 1536
__device__ float g_attn[ROWS * CH];         // 4096 x 512

// ---------------- f32x2 packed FMA helpers (PTX-only on sm_103a) ---------
__device__ __forceinline__ unsigned long long pk2(float lo, float hi) {
    unsigned long long r;
    asm("mov.b64 %0, {%1,%2};" : "=l"(r) : "f"(lo), "f"(hi));
    return r;
}
__device__ __forceinline__ void fma2(unsigned long long& d,
                                     unsigned long long a,
                                     unsigned long long b) {
    asm("fma.rn.f32x2 %0, %1, %2, %0;" : "+l"(d) : "l"(a), "l"(b));
}
__device__ __forceinline__ void upk2(unsigned long long v, float& lo, float& hi) {
    asm("mov.b64 {%0,%1}, %2;" : "=f"(lo), "=f"(hi) : "l"(v));
}

// ---------------- kernel 1: fold LoRA into weights -----------------------
__global__ void fold_weights_kernel(const float* __restrict__ wq,
                                    const float* __restrict__ Aq,
                                    const float* __restrict__ Bq,
                                    const float* __restrict__ wo,
                                    const float* __restrict__ Ao,
                                    const float* __restrict__ Bo) {
    const int T1 = CH * QKVC;
    const int T2 = CH * CH;
    int idx = blockIdx.x * blockDim.x + threadIdx.x;
    if (idx < T1) {
        int i = idx / QKVC, j = idx - i * QKVC;
        float s = 0.f;
#pragma unroll
        for (int r = 0; r < RANK; r++) s += Aq[i * RANK + r] * Bq[r * QKVC + j];
        g_wqkv_eff[idx] = wq[idx] + LSCALE * s;
    } else if (idx < T1 + T2) {
        int t = idx - T1;
        int i = t / CH, j = t - i * CH;
        float s = 0.f;
#pragma unroll
        for (int r = 0; r < RANK; r++) s += Ao[i * RANK + r] * Bo[r * CH + j];
        g_wout_eff[t] = wo[t] + LSCALE * s;
    }
}

// ---------------- kernel 2/4: tiled fp32 GEMM, 128x128x16, 8x8/thread ----
// C[M,N] = A[M,K] @ B[K,N] (+ bias). M,N multiples of 128; K multiple of 16.
__global__ __launch_bounds__(256, 2)
void gemm128_kernel(const float* __restrict__ A, const float* __restrict__ B,
                    const float* __restrict__ bias, float* __restrict__ C,
                    int M, int N, int K) {
    __shared__ float As[16][132];   // transposed: As[k][m], padded
    __shared__ float Bs[16][128];

    const int tid = threadIdx.x;
    const int bm = blockIdx.y * 128;
    const int bn = blockIdx.x * 128;
    const int ty = tid >> 4;        // 0..15 -> 8 rows each
    const int tx = tid & 15;        // 0..15 -> 8 cols each
    const int am = tid >> 2;        // 0..63
    const int ak = (tid & 3) << 2;  // 0,4,8,12
    const int bk = tid >> 5;        // 0..7
    const int bn4 = (tid & 31) << 2;

    unsigned long long acc2[8][4];
#pragma unroll
    for (int i = 0; i < 8; i++)
#pragma unroll
        for (int j = 0; j < 4; j++) acc2[i][j] = 0ull;

    for (int k0 = 0; k0 < K; k0 += 16) {
        float4 a0 = *(const float4*)&A[(bm + am) * K + k0 + ak];
        float4 a1 = *(const float4*)&A[(bm + am + 64) * K + k0 + ak];
        As[ak + 0][am] = a0.x; As[ak + 1][am] = a0.y;
        As[ak + 2][am] = a0.z; As[ak + 3][am] = a0.w;
        As[ak + 0][am + 64] = a1.x; As[ak + 1][am + 64] = a1.y;
        As[ak + 2][am + 64] = a1.z; As[ak + 3][am + 64] = a1.w;
        *(float4*)&Bs[bk][bn4]     = *(const float4*)&B[(k0 + bk) * N + bn + bn4];
        *(float4*)&Bs[bk + 8][bn4] = *(const float4*)&B[(k0 + bk + 8) * N + bn + bn4];
        __syncthreads();

#pragma unroll
        for (int kk = 0; kk < 16; kk++) {
            float4 aA = *(float4*)&As[kk][ty * 8];
            float4 aB = *(float4*)&As[kk][ty * 8 + 4];
            float4 b0 = *(float4*)&Bs[kk][tx * 8];
            float4 b1 = *(float4*)&Bs[kk][tx * 8 + 4];
            unsigned long long bb[4] = {pk2(b0.x, b0.y), pk2(b0.z, b0.w),
                                        pk2(b1.x, b1.y), pk2(b1.z, b1.w)};
            float av[8] = {aA.x, aA.y, aA.z, aA.w, aB.x, aB.y, aB.z, aB.w};
#pragma unroll
            for (int i = 0; i < 8; i++) {
                unsigned long long aa = pk2(av[i], av[i]);
#pragma unroll
                for (int j = 0; j < 4; j++) fma2(acc2[i][j], aa, bb[j]);
            }
        }
        __syncthreads();
    }

#pragma unroll
    for (int i = 0; i < 8; i++) {
        int row = bm + ty * 8 + i;
#pragma unroll
        for (int j = 0; j < 4; j++) {
            float c0, c1;
            upk2(acc2[i][j], c0, c1);
            int col = bn + tx * 8 + j * 2;
            float b0 = bias ? bias[col] : 0.f;
            float b1 = bias ? bias[col + 1] : 0.f;
            C[row * N + col]     = c0 + b0;
            C[row * N + col + 1] = c1 + b1;
        }
    }
}

// ---------------- kernel 3: windowed + global attention ------------------
// One CTA per (b, h, 64-query tile). Keys in SMEM: 128 local (window span)
// + 32 strided-global = 160. Two separate softmaxes, fused AV pass.
#define TQ 64
#define KLOC 128
#define KTOT 160
#define QP 65
#define KP 161
#define SP 68
#define SM_Q  (TQ * QP)            // 4160
#define SM_K  (DH * KP)            // 10304
#define SM_V  (KTOT * DH)          // 10240
#define SM_S  (KTOT * SP)          // 10880
#define ATTN_SMEM_FLOATS (SM_Q + SM_K + SM_V + SM_S)
#define ATTN_SMEM_BYTES  (ATTN_SMEM_FLOATS * 4)

__global__ __launch_bounds__(256, 1)
void attn_kernel() {
    extern __shared__ float sm[];
    float* Qs = sm;                 // [d][q]  stride QP
    float* Ks = Qs + SM_Q;          // [d][j]  stride KP
    float* Vs = Ks + SM_K;          // [j][d]  stride DH
    float* St = Vs + SM_V;          // [j][q]  stride SP

    const int tid = threadIdx.x;
    const int i0 = blockIdx.x * TQ;
    const int b = blockIdx.y >> 3;
    const int h = blockIdx.y & 7;
    const float scale = 0.125f;     // 1/sqrt(64)

    const float* qbase = g_qkv + (size_t)(b * SEQ) * QKVC + h * DH;
    const float* kbase = qbase + CH;
    const float* vbase = qbase + 2 * CH;

    // ---- stage Q (transposed), K (transposed), V ----
    for (int idx = tid; idx < TQ * DH; idx += 256) {
        int q = idx >> 6, d = idx & 63;
        Qs[d * QP + q] = qbase[(size_t)(i0 + q) * QKVC + d];
    }
    for (int idx = tid; idx < KTOT * DH; idx += 256) {
        int j = idx >> 6, d = idx & 63;
        int gj = (j < KLOC) ? (i0 - WIN + j) : ((j - KLOC) * WIN);
        float kv = 0.f, vv = 0.f;
        if (gj >= 0) {
            kv = kbase[(size_t)gj * QKVC + d];
            vv = vbase[(size_t)gj * QKVC + d];
        }
        Ks[d * KP + j] = kv;
        Vs[j * DH + d] = vv;
    }
    __syncthreads();

    // ---- scores: thread = 4 queries x 10 keys ----
    {
        const int ty = tid >> 4;    // query group
        const int tx = tid & 15;    // key group
        unsigned long long s2[4][5];
#pragma unroll
        for (int i = 0; i < 4; i++)
#pragma unroll
            for (int j = 0; j < 5; j++) s2[i][j] = 0ull;

        for (int kk = 0; kk < DH; kk++) {
            float qv[4], kv[10];
#pragma unroll
            for (int u = 0; u < 4; u++) qv[u] = Qs[kk * QP + ty * 4 + u];
#pragma unroll
            for (int u = 0; u < 10; u++) kv[u] = Ks[kk * KP + tx * 10 + u];
            unsigned long long k2[5];
#pragma unroll
            for (int u = 0; u < 5; u++) k2[u] = pk2(kv[2 * u], kv[2 * u + 1]);
#pragma unroll
            for (int i = 0; i < 4; i++) {
                unsigned long long aa = pk2(qv[i], qv[i]);
#pragma unroll
                for (int j = 0; j < 5; j++) fma2(s2[i][j], aa, k2[j]);
            }
        }
#pragma unroll
        for (int i = 0; i < 4; i++) {
            int q = ty * 4 + i;
#pragma unroll
            for (int j = 0; j < 5; j++) {
                float s0, s1;
                upk2(s2[i][j], s0, s1);
                int jj = tx * 10 + 2 * j;
                St[jj * SP + q]       = s0 * scale;
                St[(jj + 1) * SP + q] = s1 * scale;
            }
        }
    }
    __syncthreads();

    // ---- two softmaxes per row: 4 threads per query row ----
    {
        const int q = tid >> 2;
        const int p = tid & 3;
        const int lo = max(q, WIN - i0);
        const int hi = q + WIN;

        // local (entries 0..127)
        float m = -3.0e38f;
#pragma unroll
        for (int u = 0; u < 32; u++) {
            int lj = p * 32 + u;
            float s = St[lj * SP + q];
            if (lj >= lo && lj <= hi) m = fmaxf(m, s);
        }
        m = fmaxf(m, __shfl_xor_sync(0xffffffffu, m, 1));
        m = fmaxf(m, __shfl_xor_sync(0xffffffffu, m, 2));
        float sum = 0.f;
#pragma unroll
        for (int u = 0; u < 32; u++) {
            int lj = p * 32 + u;
            float s = St[lj * SP + q];
            float e = (lj >= lo && lj <= hi) ? __expf(s - m) : 0.f;
            St[lj * SP + q] = e;
            sum += e;
        }
        sum += __shfl_xor_sync(0xffffffffu, sum, 1);
        sum += __shfl_xor_sync(0xffffffffu, sum, 2);
        float inv = 1.0f / sum;
#pragma unroll
        for (int u = 0; u < 32; u++) {
            int lj = p * 32 + u;
            St[lj * SP + q] *= inv;
        }

        // global (entries 128..159, no mask)
        float mg = -3.0e38f;
#pragma unroll
        for (int u = 0; u < 8; u++)
            mg = fmaxf(mg, St[(KLOC + p * 8 + u) * SP + q]);
        mg = fmaxf(mg, __shfl_xor_sync(0xffffffffu, mg, 1));
        mg = fmaxf(mg, __shfl_xor_sync(0xffffffffu, mg, 2));
        float sg = 0.f;
#pragma unroll
        for (int u = 0; u < 8; u++) {
            int jj = KLOC + p * 8 + u;
            float e = __expf(St[jj * SP + q] - mg);
            St[jj * SP + q] = e;
            sg += e;
        }
        sg += __shfl_xor_sync(0xffffffffu, sg, 1);
        sg += __shfl_xor_sync(0xffffffffu, sg, 2);
        float invg = 1.0f / sg;
#pragma unroll
        for (int u = 0; u < 8; u++) {
            int jj = KLOC + p * 8 + u;
            St[jj * SP + q] *= invg;
        }
    }
    __syncthreads();

    // ---- AV: out[64q][64d] = St^T @ Vs; thread = 4q x 4d ----
    {
        const int ty = tid >> 4;
        const int tx = tid & 15;
        unsigned long long acc2[4][2];
#pragma unroll
        for (int i = 0; i < 4; i++) { acc2[i][0] = 0ull; acc2[i][1] = 0ull; }

        for (int j = 0; j < KTOT; j++) {
            float4 sv = *(float4*)&St[j * SP + ty * 4];
            float4 vv = *(float4*)&Vs[j * DH + tx * 4];
            unsigned long long v01 = pk2(vv.x, vv.y);
            unsigned long long v23 = pk2(vv.z, vv.w);
            float s4[4] = {sv.x, sv.y, sv.z, sv.w};
#pragma unroll
            for (int i = 0; i < 4; i++) {
                unsigned long long aa = pk2(s4[i], s4[i]);
                fma2(acc2[i][0], aa, v01);
                fma2(acc2[i][1], aa, v23);
            }
        }
#pragma unroll
        for (int i = 0; i < 4; i++) {
            int row = (b * SEQ + i0 + ty * 4 + i);
            float o0, o1, o2, o3;
            upk2(acc2[i][0], o0, o1);
            upk2(acc2[i][1], o2, o3);
            float* dst = g_attn + (size_t)row * CH + h * DH + tx * 4;
            dst[0] = o0; dst[1] = o1; dst[2] = o2; dst[3] = o3;
        }
    }
}

// ---------------- host launcher ------------------------------------------
extern "C" void kernel_launch(void* const* d_in, const int* in_sizes, int n_in,
                              void* d_out, int out_size) {
    const float* x      = (const float*)d_in[0];
    const float* w_qkv  = (const float*)d_in[1];
    const float* A_qkv  = (const float*)d_in[2];
    const float* B_qkv  = (const float*)d_in[3];
    const float* w_out  = (const float*)d_in[4];
    const float* b_out  = (const float*)d_in[5];
    const float* A_out  = (const float*)d_in[6];
    const float* B_out  = (const float*)d_in[7];
    float* out = (float*)d_out;

    void *p_wqkv, *p_wout, *p_qkv, *p_attn;
    cudaGetSymbolAddress(&p_wqkv, g_wqkv_eff);
    cudaGetSymbolAddress(&p_wout, g_wout_eff);
    cudaGetSymbolAddress(&p_qkv,  g_qkv);
    cudaGetSymbolAddress(&p_attn, g_attn);

    cudaFuncSetAttribute(attn_kernel,
                         cudaFuncAttributeMaxDynamicSharedMemorySize,
                         ATTN_SMEM_BYTES);

    // 1) fold LoRA into effective weights
    {
        int total = CH * QKVC + CH * CH;
        fold_weights_kernel<<<(total + 255) / 256, 256>>>(
            w_qkv, A_qkv, B_qkv, w_out, A_out, B_out);
    }
    // 2) QKV GEMM: x(4096x512) @ w_eff(512x1536)
    gemm128_kernel<<<dim3(QKVC / 128, ROWS / 128), 256>>>(
        x, (const float*)p_wqkv, nullptr, (float*)p_qkv, ROWS, QKVC, CH);
    // 3) attention
    attn_kernel<<<dim3(SEQ / TQ, BATCH * HEADS), 256, ATTN_SMEM_BYTES>>>();
    // 4) out projection: attn(4096x512) @ w_out_eff(512x512) + b_out
    gemm128_kernel<<<dim3(CH / 128, ROWS / 128), 256>>>(
        (const float*)p_attn, (const float*)p_wout, b_out, out, ROWS, CH, CH);
}

// round 16
// speedup vs baseline: 1.4411x; 1.4411x over previous
#include <cuda_runtime.h>
#include <cuda_bf16.h>
#include <cstdint>
#include <math.h>

#define BATCH 2
#define SEQ   2048
#define CH    512
#define HEADS 8
#define DH    64
#define WIN   64
#define RANK  8
#define LSCALE 0.25f               // 2.0 / R
#define QKVC  (3 * CH)             // 1536
#define ROWS  (BATCH * SEQ)        // 4096

// ---------------- device scratch (no allocations allowed) ----------------
__device__ float g_qkv[ROWS * QKVC];                      // fp32 qkv
__device__ __nv_bfloat16 g_x_hi[ROWS * CH];
__device__ __nv_bfloat16 g_x_lo[ROWS * CH];
__device__ __nv_bfloat16 g_wqkvT_hi[QKVC * CH];           // [n][k] transposed eff weight
__device__ __nv_bfloat16 g_wqkvT_lo[QKVC * CH];
__device__ __nv_bfloat16 g_woutT_hi[CH * CH];
__device__ __nv_bfloat16 g_woutT_lo[CH * CH];
__device__ __nv_bfloat16 g_attn_hi[ROWS * CH];
__device__ __nv_bfloat16 g_attn_lo[ROWS * CH];

// ---------------- PTX helpers (plain sm_80-class ISA only) ---------------
__device__ __forceinline__ uint32_t su32(const void* p) {
    return (uint32_t)__cvta_generic_to_shared(p);
}
__device__ __forceinline__ void ldmx4(uint32_t* r, uint32_t addr) {
    asm volatile("ldmatrix.sync.aligned.m8n8.x4.shared.b16 {%0,%1,%2,%3}, [%4];"
                 : "=r"(r[0]), "=r"(r[1]), "=r"(r[2]), "=r"(r[3]) : "r"(addr));
}
__device__ __forceinline__ void mma16816(float* d, const uint32_t* a,
                                         uint32_t b0, uint32_t b1) {
    asm volatile("mma.sync.aligned.m16n8k16.row.col.f32.bf16.bf16.f32 "
                 "{%0,%1,%2,%3}, {%4,%5,%6,%7}, {%8,%9}, {%0,%1,%2,%3};"
                 : "+f"(d[0]), "+f"(d[1]), "+f"(d[2]), "+f"(d[3])
                 : "r"(a[0]), "r"(a[1]), "r"(a[2]), "r"(a[3]), "r"(b0), "r"(b1));
}

// f32x2 packed FMA helpers (attention kernel)
__device__ __forceinline__ unsigned long long pk2(float lo, float hi) {
    unsigned long long r;
    asm("mov.b64 %0, {%1,%2};" : "=l"(r) : "f"(lo), "f"(hi));
    return r;
}
__device__ __forceinline__ void fma2(unsigned long long& d,
                                     unsigned long long a, unsigned long long b) {
    asm("fma.rn.f32x2 %0, %1, %2, %0;" : "+l"(d) : "l"(a), "l"(b));
}
__device__ __forceinline__ void upk2(unsigned long long v, float& lo, float& hi) {
    asm("mov.b64 {%0,%1}, %2;" : "=f"(lo), "=f"(hi) : "l"(v));
}

__device__ __forceinline__ void split_bf16(float v, __nv_bfloat16& h, __nv_bfloat16& l) {
    h = __float2bfloat16(v);
    l = __float2bfloat16(v - __bfloat162float(h));
}

// ---------------- kernel: fold LoRA + transpose + bf16-split weights -----
__global__ void fold_kernel(const float* __restrict__ wq, const float* __restrict__ Aq,
                            const float* __restrict__ Bq, const float* __restrict__ wo,
                            const float* __restrict__ Ao, const float* __restrict__ Bo) {
    const int T1 = QKVC * CH;
    int idx = blockIdx.x * blockDim.x + threadIdx.x;
    if (idx < T1) {
        int n = idx >> 9, k = idx & 511;
        float s = 0.f;
#pragma unroll
        for (int r = 0; r < RANK; r++) s += Aq[k * RANK + r] * Bq[r * QKVC + n];
        float w = wq[k * QKVC + n] + LSCALE * s;
        split_bf16(w, g_wqkvT_hi[idx], g_wqkvT_lo[idx]);
    } else if (idx < T1 + CH * CH) {
        int t = idx - T1;
        int n = t >> 9, k = t & 511;
        float s = 0.f;
#pragma unroll
        for (int r = 0; r < RANK; r++) s += Ao[k * RANK + r] * Bo[r * CH + n];
        float w = wo[k * CH + n] + LSCALE * s;
        split_bf16(w, g_woutT_hi[t], g_woutT_lo[t]);
    }
}

// ---------------- kernel: x -> bf16 hi/lo --------------------------------
__global__ void convert_x_kernel(const float* __restrict__ x) {
    int i = blockIdx.x * blockDim.x + threadIdx.x;   // over ROWS*CH/4
    float4 v = ((const float4*)x)[i];
    __nv_bfloat16 h0, h1, h2, h3, l0, l1, l2, l3;
    split_bf16(v.x, h0, l0); split_bf16(v.y, h1, l1);
    split_bf16(v.z, h2, l2); split_bf16(v.w, h3, l3);
    __nv_bfloat162 a, b;
    a.x = h0; a.y = h1; b.x = h2; b.y = h3;
    ((__nv_bfloat162*)g_x_hi)[2 * i] = a;
    ((__nv_bfloat162*)g_x_hi)[2 * i + 1] = b;
    a.x = l0; a.y = l1; b.x = l2; b.y = l3;
    ((__nv_bfloat162*)g_x_lo)[2 * i] = a;
    ((__nv_bfloat162*)g_x_lo)[2 * i + 1] = b;
}

// ---------------- bf16-split mma.sync GEMM (register-staged pipeline) ----
// C[4096, Nn] = (Ah+Al)[4096,512] @ (Bh+Bl)^T via hi*hi + hi*lo + lo*hi.
// CTA = 128x128, 8 warps (4m x 2n), warp tile 32x64. K' = 1536 in 48
// chunks of 32. Single SMEM buffer; next chunk prefetched into registers
// (LDG issued before compute, consumed after the barrier).
#define SA 40                       // padded SMEM row stride (bf16)
#define NCHUNK 48

__global__ __launch_bounds__(256)
void gemm_mma_kernel(const __nv_bfloat16* __restrict__ Ah, const __nv_bfloat16* __restrict__ Al,
                     const __nv_bfloat16* __restrict__ Bh, const __nv_bfloat16* __restrict__ Bl,
                     const float* __restrict__ bias, float* __restrict__ C, int Nn) {
    __shared__ __nv_bfloat16 As[128 * SA];
    __shared__ __nv_bfloat16 Bs[128 * SA];

    const int tid  = threadIdx.x;
    const int wid  = tid >> 5;
    const int lane = tid & 31;
    const int bm = blockIdx.y * 128;
    const int bn = blockIdx.x * 128;
    const int wr = wid & 3;          // warp m: wr*32
    const int wc = wid >> 2;         // warp n: wc*64

    // per-thread load coords: each thread owns 32 bf16 of one row half
    const int lr = tid >> 1;              // row 0..127
    const int ls = (tid & 1) * 16;        // col offset in bf16 (0 or 16)

    float acc[2][8][4];
#pragma unroll
    for (int t = 0; t < 2; t++)
#pragma unroll
        for (int n = 0; n < 8; n++)
#pragma unroll
            for (int j = 0; j < 4; j++) acc[t][n][j] = 0.f;

    uint4 ra0, ra1, rb0, rb1;

    // prologue: LDG chunk 0 into registers
    {
        const __nv_bfloat16* a_src = Ah + (size_t)(bm + lr) * CH + ls;
        const __nv_bfloat16* b_src = Bh + (size_t)(bn + lr) * CH + ls;
        ra0 = *(const uint4*)a_src;
        ra1 = *(const uint4*)(a_src + 8);
        rb0 = *(const uint4*)b_src;
        rb1 = *(const uint4*)(b_src + 8);
    }

    const int lrow = lane & 15;
    const int lcol = (lane >> 4) << 3;

    for (int c = 0; c < NCHUNK; c++) {
        // store staged chunk c to SMEM
        *(uint4*)&As[lr * SA + ls]     = ra0;
        *(uint4*)&As[lr * SA + ls + 8] = ra1;
        *(uint4*)&Bs[lr * SA + ls]     = rb0;
        *(uint4*)&Bs[lr * SA + ls + 8] = rb1;
        __syncthreads();

        // prefetch chunk c+1 into registers (overlaps with compute below)
        if (c + 1 < NCHUNK) {
            int cn = c + 1;
            int seg = cn >> 4;
            int kk = (cn & 15) << 5;
            const __nv_bfloat16* Ap = (seg < 2) ? Ah : Al;
            const __nv_bfloat16* Bp = (seg == 0) ? Bh : ((seg == 1) ? Bl : Bh);
            const __nv_bfloat16* a_src = Ap + (size_t)(bm + lr) * CH + kk + ls;
            const __nv_bfloat16* b_src = Bp + (size_t)(bn + lr) * CH + kk + ls;
            ra0 = *(const uint4*)a_src;
            ra1 = *(const uint4*)(a_src + 8);
            rb0 = *(const uint4*)b_src;
            rb1 = *(const uint4*)(b_src + 8);
        }

        // compute chunk c from SMEM
#pragma unroll
        for (int k16 = 0; k16 < 2; k16++) {
            uint32_t af[2][4];
#pragma unroll
            for (int t = 0; t < 2; t++)
                ldmx4(af[t], su32(&As[(wr * 32 + t * 16 + lrow) * SA + k16 * 16 + lcol]));
            uint32_t bf[4][4];
#pragma unroll
            for (int p = 0; p < 4; p++)
                ldmx4(bf[p], su32(&Bs[(wc * 64 + p * 16 + lrow) * SA + k16 * 16 + lcol]));
#pragma unroll
            for (int t = 0; t < 2; t++)
#pragma unroll
                for (int n = 0; n < 8; n++)
                    mma16816(acc[t][n], af[t], bf[n >> 1][n & 1], bf[n >> 1][(n & 1) + 2]);
        }
        __syncthreads();
    }

    // epilogue: fragment layout c0,c1=(row lane/4, col 2*(lane%4)+{0,1}), c2,c3=row+8
#pragma unroll
    for (int t = 0; t < 2; t++) {
        int row0 = bm + wr * 32 + t * 16 + (lane >> 2);
#pragma unroll
        for (int n = 0; n < 8; n++) {
            int col = bn + wc * 64 + n * 8 + (lane & 3) * 2;
            float b0 = bias ? bias[col] : 0.f;
            float b1 = bias ? bias[col + 1] : 0.f;
            float2 v0 = {acc[t][n][0] + b0, acc[t][n][1] + b1};
            float2 v1 = {acc[t][n][2] + b0, acc[t][n][3] + b1};
            *(float2*)&C[(size_t)row0 * Nn + col]       = v0;
            *(float2*)&C[(size_t)(row0 + 8) * Nn + col] = v1;
        }
    }
}

// ---------------- kernel: windowed + global attention --------------------
#define TQ 64
#define KLOC 128
#define KTOT 160
#define QP 65
#define KP 161
#define SP 68
#define SM_Q  (TQ * QP)
#define SM_K  (DH * KP)
#define SM_V  (KTOT * DH)
#define SM_S  (KTOT * SP)
#define ATTN_SMEM_FLOATS (SM_Q + SM_K + SM_V + SM_S)
#define ATTN_SMEM_BYTES  (ATTN_SMEM_FLOATS * 4)

__global__ __launch_bounds__(256, 1)
void attn_kernel() {
    extern __shared__ float sm[];
    float* Qs = sm;                 // [d][q]  stride QP
    float* Ks = Qs + SM_Q;          // [d][j]  stride KP
    float* Vs = Ks + SM_K;          // [j][d]  stride DH
    float* St = Vs + SM_V;          // [j][q]  stride SP

    const int tid = threadIdx.x;
    const int i0 = blockIdx.x * TQ;
    const int b = blockIdx.y >> 3;
    const int h = blockIdx.y & 7;
    const float scale = 0.125f;

    const float* qbase = g_qkv + (size_t)(b * SEQ) * QKVC + h * DH;
    const float* kbase = qbase + CH;
    const float* vbase = qbase + 2 * CH;

    for (int idx = tid; idx < TQ * DH; idx += 256) {
        int q = idx >> 6, d = idx & 63;
        Qs[d * QP + q] = qbase[(size_t)(i0 + q) * QKVC + d];
    }
    for (int idx = tid; idx < KTOT * DH; idx += 256) {
        int j = idx >> 6, d = idx & 63;
        int gj = (j < KLOC) ? (i0 - WIN + j) : ((j - KLOC) * WIN);
        float kv = 0.f, vv = 0.f;
        if (gj >= 0) {
            kv = kbase[(size_t)gj * QKVC + d];
            vv = vbase[(size_t)gj * QKVC + d];
        }
        Ks[d * KP + j] = kv;
        Vs[j * DH + d] = vv;
    }
    __syncthreads();

    // scores: thread = 4 queries x 10 keys
    {
        const int ty = tid >> 4;
        const int tx = tid & 15;
        unsigned long long s2[4][5];
#pragma unroll
        for (int i = 0; i < 4; i++)
#pragma unroll
            for (int j = 0; j < 5; j++) s2[i][j] = 0ull;

        for (int kk = 0; kk < DH; kk++) {
            float qv[4], kv[10];
#pragma unroll
            for (int u = 0; u < 4; u++) qv[u] = Qs[kk * QP + ty * 4 + u];
#pragma unroll
            for (int u = 0; u < 10; u++) kv[u] = Ks[kk * KP + tx * 10 + u];
            unsigned long long k2[5];
#pragma unroll
            for (int u = 0; u < 5; u++) k2[u] = pk2(kv[2 * u], kv[2 * u + 1]);
#pragma unroll
            for (int i = 0; i < 4; i++) {
                unsigned long long aa = pk2(qv[i], qv[i]);
#pragma unroll
                for (int j = 0; j < 5; j++) fma2(s2[i][j], aa, k2[j]);
            }
        }
#pragma unroll
        for (int i = 0; i < 4; i++) {
            int q = ty * 4 + i;
#pragma unroll
            for (int j = 0; j < 5; j++) {
                float s0, s1;
                upk2(s2[i][j], s0, s1);
                int jj = tx * 10 + 2 * j;
                St[jj * SP + q]       = s0 * scale;
                St[(jj + 1) * SP + q] = s1 * scale;
            }
        }
    }
    __syncthreads();

    // two softmaxes per row: 4 threads per query row
    {
        const int q = tid >> 2;
        const int p = tid & 3;
        const int lo = max(q, WIN - i0);
        const int hi = q + WIN;

        float m = -3.0e38f;
#pragma unroll
        for (int u = 0; u < 32; u++) {
            int lj = p * 32 + u;
            float s = St[lj * SP + q];
            if (lj >= lo && lj <= hi) m = fmaxf(m, s);
        }
        m = fmaxf(m, __shfl_xor_sync(0xffffffffu, m, 1));
        m = fmaxf(m, __shfl_xor_sync(0xffffffffu, m, 2));
        float sum = 0.f;
#pragma unroll
        for (int u = 0; u < 32; u++) {
            int lj = p * 32 + u;
            float s = St[lj * SP + q];
            float e = (lj >= lo && lj <= hi) ? __expf(s - m) : 0.f;
            St[lj * SP + q] = e;
            sum += e;
        }
        sum += __shfl_xor_sync(0xffffffffu, sum, 1);
        sum += __shfl_xor_sync(0xffffffffu, sum, 2);
        float inv = 1.0f / sum;
#pragma unroll
        for (int u = 0; u < 32; u++) {
            int lj = p * 32 + u;
            St[lj * SP + q] *= inv;
        }

        float mg = -3.0e38f;
#pragma unroll
        for (int u = 0; u < 8; u++)
            mg = fmaxf(mg, St[(KLOC + p * 8 + u) * SP + q]);
        mg = fmaxf(mg, __shfl_xor_sync(0xffffffffu, mg, 1));
        mg = fmaxf(mg, __shfl_xor_sync(0xffffffffu, mg, 2));
        float sg = 0.f;
#pragma unroll
        for (int u = 0; u < 8; u++) {
            int jj = KLOC + p * 8 + u;
            float e = __expf(St[jj * SP + q] - mg);
            St[jj * SP + q] = e;
            sg += e;
        }
        sg += __shfl_xor_sync(0xffffffffu, sg, 1);
        sg += __shfl_xor_sync(0xffffffffu, sg, 2);
        float invg = 1.0f / sg;
#pragma unroll
        for (int u = 0; u < 8; u++) {
            int jj = KLOC + p * 8 + u;
            St[jj * SP + q] *= invg;
        }
    }
    __syncthreads();

    // AV: out[64q][64d] = St^T @ Vs; thread = 4q x 4d; write bf16 hi/lo
    {
        const int ty = tid >> 4;
        const int tx = tid & 15;
        unsigned long long acc2[4][2];
#pragma unroll
        for (int i = 0; i < 4; i++) { acc2[i][0] = 0ull; acc2[i][1] = 0ull; }

        for (int j = 0; j < KTOT; j++) {
            float4 sv = *(float4*)&St[j * SP + ty * 4];
            float4 vv = *(float4*)&Vs[j * DH + tx * 4];
            unsigned long long v01 = pk2(vv.x, vv.y);
            unsigned long long v23 = pk2(vv.z, vv.w);
            float s4[4] = {sv.x, sv.y, sv.z, sv.w};
#pragma unroll
            for (int i = 0; i < 4; i++) {
                unsigned long long aa = pk2(s4[i], s4[i]);
                fma2(acc2[i][0], aa, v01);
                fma2(acc2[i][1], aa, v23);
            }
        }
#pragma unroll
        for (int i = 0; i < 4; i++) {
            int row = (b * SEQ + i0 + ty * 4 + i);
            float o[4];
            upk2(acc2[i][0], o[0], o[1]);
            upk2(acc2[i][1], o[2], o[3]);
            size_t base = (size_t)row * CH + h * DH + tx * 4;
            __nv_bfloat16 hh[4], ll[4];
#pragma unroll
            for (int u = 0; u < 4; u++) split_bf16(o[u], hh[u], ll[u]);
            __nv_bfloat162 p0, p1;
            p0.x = hh[0]; p0.y = hh[1]; p1.x = hh[2]; p1.y = hh[3];
            *(__nv_bfloat162*)&g_attn_hi[base]     = p0;
            *(__nv_bfloat162*)&g_attn_hi[base + 2] = p1;
            p0.x = ll[0]; p0.y = ll[1]; p1.x = ll[2]; p1.y = ll[3];
            *(__nv_bfloat162*)&g_attn_lo[base]     = p0;
            *(__nv_bfloat162*)&g_attn_lo[base + 2] = p1;
        }
    }
}

// ---------------- host launcher ------------------------------------------
extern "C" void kernel_launch(void* const* d_in, const int* in_sizes, int n_in,
                              void* d_out, int out_size) {
    const float* x      = (const float*)d_in[0];
    const float* w_qkv  = (const float*)d_in[1];
    const float* A_qkv  = (const float*)d_in[2];
    const float* B_qkv  = (const float*)d_in[3];
    const float* w_out  = (const float*)d_in[4];
    const float* b_out  = (const float*)d_in[5];
    const float* A_out  = (const float*)d_in[6];
    const float* B_out  = (const float*)d_in[7];
    float* out = (float*)d_out;

    void *p_qkv, *p_xh, *p_xl, *p_wqh, *p_wql, *p_woh, *p_wol, *p_ah, *p_al;
    cudaGetSymbolAddress(&p_qkv, g_qkv);
    cudaGetSymbolAddress(&p_xh, g_x_hi);
    cudaGetSymbolAddress(&p_xl, g_x_lo);
    cudaGetSymbolAddress(&p_wqh, g_wqkvT_hi);
    cudaGetSymbolAddress(&p_wql, g_wqkvT_lo);
    cudaGetSymbolAddress(&p_woh, g_woutT_hi);
    cudaGetSymbolAddress(&p_wol, g_woutT_lo);
    cudaGetSymbolAddress(&p_ah, g_attn_hi);
    cudaGetSymbolAddress(&p_al, g_attn_lo);

    cudaFuncSetAttribute(attn_kernel,
                         cudaFuncAttributeMaxDynamicSharedMemorySize,
                         ATTN_SMEM_BYTES);

    // 1) fold LoRA into transposed bf16-split weights
    {
        int total = QKVC * CH + CH * CH;
        fold_kernel<<<(total + 255) / 256, 256>>>(w_qkv, A_qkv, B_qkv,
                                                  w_out, A_out, B_out);
    }
    // 2) x -> bf16 hi/lo
    convert_x_kernel<<<(ROWS * CH / 4) / 256, 256>>>(x);
    // 3) QKV GEMM (HMMA): 4096x1536, K'=1536
    gemm_mma_kernel<<<dim3(QKVC / 128, ROWS / 128), 256>>>(
        (const __nv_bfloat16*)p_xh, (const __nv_bfloat16*)p_xl,
        (const __nv_bfloat16*)p_wqh, (const __nv_bfloat16*)p_wql,
        nullptr, (float*)p_qkv, QKVC);
    // 4) attention (writes bf16 hi/lo directly)
    attn_kernel<<<dim3(SEQ / TQ, BATCH * HEADS), 256, ATTN_SMEM_BYTES>>>();
    // 5) out projection (HMMA): 4096x512 + bias
    gemm_mma_kernel<<<dim3(CH / 128, ROWS / 128), 256>>>(
        (const __nv_bfloat16*)p_ah, (const __nv_bfloat16*)p_al,
        (const __nv_bfloat16*)p_woh, (const __nv_bfloat16*)p_wol,
        b_out, out, CH);
}